// round 5
// baseline (speedup 1.0000x reference)
#include <cuda_runtime.h>
#include <cstdint>

#define BB 4
#define NN 1024
#define DD 768
#define HH 12
#define HD 64
#define BH 48
#define KTH 104857

// ---------------- scratch ----------------
__device__ float g_qkv[4096 * 2304];
__device__ float g_attn[(size_t)48 * 1024 * 1024];
__device__ float g_ao[4096 * 768];
__device__ unsigned g_hist[48 * 2048];
__device__ unsigned g_sel[48];
__device__ int g_krem[48];
__device__ float g_thr[48];
__device__ unsigned g_cand[(size_t)48 * 1048576];
__device__ int g_ccnt[48];
__device__ int g_rcnt[48 * 1024];

__device__ __forceinline__ unsigned fkey(float f) {
    unsigned u = __float_as_uint(f);
    return (u & 0x80000000u) ? ~u : (u ^ 0x80000000u);
}

// ---------------------------------------------------------------------------
// Generic GEMM: C[M,N] = A[M,K] @ B[K,N] + bias[N]  (round-1 proven version)
// ---------------------------------------------------------------------------
__global__ void __launch_bounds__(256) gemm128_bias(
    const float* __restrict__ A, const float* __restrict__ Bm,
    const float* __restrict__ bias, float* __restrict__ C,
    int M, int Nn, int K) {
    __shared__ float As[8][128];
    __shared__ float Bs[8][128];
    int t = threadIdx.x;
    int n0 = blockIdx.x * 128;
    int m0 = blockIdx.y * 128;
    int tx = t & 15, ty = t >> 4;
    float acc[8][8];
#pragma unroll
    for (int i = 0; i < 8; i++)
#pragma unroll
        for (int j = 0; j < 8; j++) acc[i][j] = 0.f;

    int arow = t >> 1, acol = (t & 1) * 4;
    int brow = t >> 5, bcol = (t & 31) * 4;

    for (int k0 = 0; k0 < K; k0 += 8) {
        float4 av = *(const float4*)(A + (size_t)(m0 + arow) * K + k0 + acol);
        As[acol + 0][arow] = av.x;
        As[acol + 1][arow] = av.y;
        As[acol + 2][arow] = av.z;
        As[acol + 3][arow] = av.w;
        float4 bv = *(const float4*)(Bm + (size_t)(k0 + brow) * Nn + n0 + bcol);
        *(float4*)&Bs[brow][bcol] = bv;
        __syncthreads();
#pragma unroll
        for (int kk = 0; kk < 8; kk++) {
            float a[8], b[8];
#pragma unroll
            for (int i = 0; i < 8; i++) a[i] = As[kk][ty * 8 + i];
#pragma unroll
            for (int j = 0; j < 8; j++) b[j] = Bs[kk][tx * 8 + j];
#pragma unroll
            for (int i = 0; i < 8; i++)
#pragma unroll
                for (int j = 0; j < 8; j++) acc[i][j] += a[i] * b[j];
        }
        __syncthreads();
    }
    float bb[8];
#pragma unroll
    for (int j = 0; j < 8; j++) bb[j] = bias[n0 + tx * 8 + j];
#pragma unroll
    for (int i = 0; i < 8; i++) {
        int row = m0 + ty * 8 + i;
#pragma unroll
        for (int j0 = 0; j0 < 8; j0 += 4) {
            float4 v;
            v.x = acc[i][j0 + 0] + bb[j0 + 0];
            v.y = acc[i][j0 + 1] + bb[j0 + 1];
            v.z = acc[i][j0 + 2] + bb[j0 + 2];
            v.w = acc[i][j0 + 3] + bb[j0 + 3];
            *(float4*)(C + (size_t)row * Nn + n0 + tx * 8 + j0) = v;
        }
    }
}

// ---------------------------------------------------------------------------
// Scores: S[bh][n][m] = 0.125 * sum_d Q[n,d] K[m,d]  + fused pass-0 histogram
// ---------------------------------------------------------------------------
__global__ void __launch_bounds__(256) gemm_scores() {
    __shared__ float Qs[8][128];
    __shared__ float Ks[8][128];
    __shared__ unsigned hsm[2048];
    int bh = blockIdx.z;
    int b = bh / HH, h = bh % HH;
    const float* Q = g_qkv + (size_t)b * NN * 2304 + h * HD;
    const float* Kp = g_qkv + (size_t)b * NN * 2304 + 768 + h * HD;
    float* S = g_attn + (size_t)bh * NN * NN;

    int t = threadIdx.x;
    int m0 = blockIdx.x * 128;
    int n0 = blockIdx.y * 128;
    int tx = t & 15, ty = t >> 4;
    for (int j = t; j < 2048; j += 256) hsm[j] = 0u;
    float acc[8][8];
#pragma unroll
    for (int i = 0; i < 8; i++)
#pragma unroll
        for (int j = 0; j < 8; j++) acc[i][j] = 0.f;

    int r = t >> 1, c4 = (t & 1) * 4;

    for (int d0 = 0; d0 < HD; d0 += 8) {
        float4 qv = *(const float4*)(Q + (size_t)(n0 + r) * 2304 + d0 + c4);
        Qs[c4 + 0][r] = qv.x; Qs[c4 + 1][r] = qv.y;
        Qs[c4 + 2][r] = qv.z; Qs[c4 + 3][r] = qv.w;
        float4 kv = *(const float4*)(Kp + (size_t)(m0 + r) * 2304 + d0 + c4);
        Ks[c4 + 0][r] = kv.x; Ks[c4 + 1][r] = kv.y;
        Ks[c4 + 2][r] = kv.z; Ks[c4 + 3][r] = kv.w;
        __syncthreads();
#pragma unroll
        for (int kk = 0; kk < 8; kk++) {
            float a[8], bvv[8];
#pragma unroll
            for (int i = 0; i < 8; i++) a[i] = Qs[kk][ty * 8 + i];
#pragma unroll
            for (int j = 0; j < 8; j++) bvv[j] = Ks[kk][tx * 8 + j];
#pragma unroll
            for (int i = 0; i < 8; i++)
#pragma unroll
                for (int j = 0; j < 8; j++) acc[i][j] += a[i] * bvv[j];
        }
        __syncthreads();
    }
#pragma unroll
    for (int i = 0; i < 8; i++) {
        int row = n0 + ty * 8 + i;
#pragma unroll
        for (int j0 = 0; j0 < 8; j0 += 4) {
            float4 v;
            v.x = acc[i][j0 + 0] * 0.125f;
            v.y = acc[i][j0 + 1] * 0.125f;
            v.z = acc[i][j0 + 2] * 0.125f;
            v.w = acc[i][j0 + 3] * 0.125f;
            atomicAdd(&hsm[fkey(v.x) >> 21], 1u);
            atomicAdd(&hsm[fkey(v.y) >> 21], 1u);
            atomicAdd(&hsm[fkey(v.z) >> 21], 1u);
            atomicAdd(&hsm[fkey(v.w) >> 21], 1u);
            *(float4*)(S + (size_t)row * NN + m0 + tx * 8 + j0) = v;
        }
    }
    __syncthreads();
    unsigned* gh = g_hist + bh * 2048;
    for (int j = t; j < 2048; j += 256) {
        unsigned c = hsm[j];
        if (c) atomicAdd(&gh[j], c);
    }
}

// ---------------------------------------------------------------------------
// Selection: init -> scan -> candidate gather -> final select
// ---------------------------------------------------------------------------
__global__ void sel_init() {
    int bh = blockIdx.x, t = threadIdx.x;
    for (int j = t; j < 2048; j += 256) g_hist[bh * 2048 + j] = 0u;
    if (t == 0) g_ccnt[bh] = 0;
}

__global__ void scan0() {
    int bh = blockIdx.x, t = threadIdx.x;
    __shared__ unsigned ssum[256];
    __shared__ int s_sel;
    __shared__ unsigned s_kin;
    const unsigned* hist = g_hist + bh * 2048;
    unsigned loc[8], lsum = 0;
#pragma unroll
    for (int i = 0; i < 8; i++) { loc[i] = hist[t * 8 + i]; lsum += loc[i]; }
    ssum[t] = lsum;
    __syncthreads();
    if (t == 0) {
        unsigned k = KTH, cum = 0, kin = k;
        int sel = 255;
        for (int i = 0; i < 256; i++) {
            if (cum + ssum[i] >= k) { sel = i; kin = k - cum; break; }
            cum += ssum[i];
        }
        s_sel = sel; s_kin = kin;
    }
    __syncthreads();
    if (t == s_sel) {
        unsigned kk = s_kin, cum = 0, d = t * 8 + 7, knew = kk;
#pragma unroll
        for (int i = 0; i < 8; i++) {
            if (cum + loc[i] >= kk) { d = t * 8 + i; knew = kk - cum; break; }
            cum += loc[i];
        }
        g_sel[bh] = d;
        g_krem[bh] = (int)knew;
    }
}

__device__ __forceinline__ void push_cand(unsigned key, unsigned sel, unsigned* cand,
                                          int* cnt, unsigned lane) {
    bool m = (key >> 21) == sel;
    unsigned bal = __ballot_sync(0xffffffffu, m);
    if (bal) {
        int leader = __ffs(bal) - 1;
        int base = 0;
        if ((int)lane == leader) base = atomicAdd(cnt, __popc(bal));
        base = __shfl_sync(0xffffffffu, base, leader);
        if (m) cand[base + __popc(bal & ((1u << lane) - 1u))] = key;
    }
}

__global__ void cand_pass() {
    int bh = blockIdx.y, t = threadIdx.x;
    unsigned lane = t & 31;
    unsigned sel = g_sel[bh];
    unsigned* cand = g_cand + (size_t)bh * 1048576;
    int* cnt = &g_ccnt[bh];
    const float4* Sp = (const float4*)(g_attn + (size_t)bh * 1048576) +
                       (size_t)blockIdx.x * 8192;
    for (int i = 0; i < 32; i++) {
        float4 v = Sp[i * 256 + t];
        push_cand(fkey(v.x), sel, cand, cnt, lane);
        push_cand(fkey(v.y), sel, cand, cnt, lane);
        push_cand(fkey(v.z), sel, cand, cnt, lane);
        push_cand(fkey(v.w), sel, cand, cnt, lane);
    }
}

__global__ void sel_final() {
    int bh = blockIdx.x, t = threadIdx.x;
    __shared__ unsigned sh[2048];
    __shared__ unsigned ssum[256];
    __shared__ int s_sel;
    __shared__ unsigned s_kin;
    __shared__ unsigned s_b1, s_k2;
    int cnt = g_ccnt[bh];
    const unsigned* cand = g_cand + (size_t)bh * 1048576;

    for (int j = t; j < 2048; j += 256) sh[j] = 0u;
    __syncthreads();
    for (int i = t; i < cnt; i += 256) atomicAdd(&sh[(cand[i] >> 10) & 2047u], 1u);
    __syncthreads();
    {
        unsigned loc[8], lsum = 0;
#pragma unroll
        for (int i = 0; i < 8; i++) { loc[i] = sh[t * 8 + i]; lsum += loc[i]; }
        ssum[t] = lsum;
        __syncthreads();
        if (t == 0) {
            unsigned k = (unsigned)g_krem[bh], cum = 0, kin = k;
            int sel = 255;
            for (int i = 0; i < 256; i++) {
                if (cum + ssum[i] >= k) { sel = i; kin = k - cum; break; }
                cum += ssum[i];
            }
            s_sel = sel; s_kin = kin;
        }
        __syncthreads();
        if (t == s_sel) {
            unsigned kk = s_kin, cum = 0, d = t * 8 + 7, knew = kk;
#pragma unroll
            for (int i = 0; i < 8; i++) {
                if (cum + loc[i] >= kk) { d = t * 8 + i; knew = kk - cum; break; }
                cum += loc[i];
            }
            s_b1 = d; s_k2 = knew;
        }
        __syncthreads();
    }
    unsigned b1 = s_b1;
    __syncthreads();

    for (int j = t; j < 1024; j += 256) sh[j] = 0u;
    __syncthreads();
    for (int i = t; i < cnt; i += 256) {
        unsigned ky = cand[i];
        if (((ky >> 10) & 2047u) == b1) atomicAdd(&sh[ky & 1023u], 1u);
    }
    __syncthreads();
    {
        unsigned loc[4], lsum = 0;
#pragma unroll
        for (int i = 0; i < 4; i++) { loc[i] = sh[t * 4 + i]; lsum += loc[i]; }
        ssum[t] = lsum;
        __syncthreads();
        if (t == 0) {
            unsigned k = s_k2, cum = 0, kin = k;
            int sel = 255;
            for (int i = 0; i < 256; i++) {
                if (cum + ssum[i] >= k) { sel = i; kin = k - cum; break; }
                cum += ssum[i];
            }
            s_sel = sel; s_kin = kin;
        }
        __syncthreads();
        if (t == s_sel) {
            unsigned kk = s_kin, cum = 0, d = t * 4 + 3;
#pragma unroll
            for (int i = 0; i < 4; i++) {
                if (cum + loc[i] >= kk) { d = t * 4 + i; break; }
                cum += loc[i];
            }
            unsigned key = (g_sel[bh] << 21) | (b1 << 10) | d;
            unsigned bits = (key & 0x80000000u) ? (key ^ 0x80000000u) : ~key;
            g_thr[bh] = __uint_as_float(bits);
        }
    }
}

// ---------------------------------------------------------------------------
// Masked softmax + ORDERED compaction: writes (col, prob) lists per row.
// Probs into g_attn row prefix (in place), cols into g_cand row region.
// ---------------------------------------------------------------------------
__global__ void __launch_bounds__(256) softmax_compact() {
    int row = blockIdx.x, bh = row >> 10;
    float thr = g_thr[bh];
    float* S = g_attn + (size_t)row * NN;
    unsigned* Cc = g_cand + (size_t)row * NN;
    int t = threadIdx.x;
    unsigned lane = t & 31, w = t >> 5;
    __shared__ float red[8];
    __shared__ int wtot[8];
    __shared__ int wbase[9];

    float4 vv = *(const float4*)(S + t * 4);
    float v[4] = {vv.x, vv.y, vv.z, vv.w};
    bool keep[4];
    int lc = 0;
    float mx = -3.0e38f;
#pragma unroll
    for (int i = 0; i < 4; i++) {
        keep[i] = v[i] > thr;
        if (keep[i]) { mx = fmaxf(mx, v[i]); lc++; }
    }
#pragma unroll
    for (int o = 16; o; o >>= 1) mx = fmaxf(mx, __shfl_xor_sync(0xffffffffu, mx, o));
    if (lane == 0) red[w] = mx;
    __syncthreads();
    float m = red[0];
#pragma unroll
    for (int i = 1; i < 8; i++) m = fmaxf(m, red[i]);

    float e[4], s = 0.f;
#pragma unroll
    for (int i = 0; i < 4; i++) {
        e[i] = keep[i] ? __expf(v[i] - m) : 0.f;
        s += e[i];
    }
#pragma unroll
    for (int o = 16; o; o >>= 1) s += __shfl_xor_sync(0xffffffffu, s, o);
    __syncthreads();
    if (lane == 0) red[w] = s;

    // ordered compaction offsets: warp scan of per-thread keep counts
    int off = lc;
#pragma unroll
    for (int o = 1; o < 32; o <<= 1) {
        int y = __shfl_up_sync(0xffffffffu, off, o);
        if ((int)lane >= o) off += y;
    }
    if (lane == 31) wtot[w] = off;
    int excl = off - lc;
    __syncthreads();
    if (t == 0) {
        int acc = 0;
#pragma unroll
        for (int i = 0; i < 8; i++) { wbase[i] = acc; acc += wtot[i]; }
        wbase[8] = acc;
    }
    __syncthreads();
    int total = wbase[8];

    if (total > 0) {
        float tot = 0.f;
#pragma unroll
        for (int i = 0; i < 8; i++) tot += red[i];
        float inv = 1.f / tot;
        int pos = wbase[w] + excl;
#pragma unroll
        for (int i = 0; i < 4; i++) {
            if (keep[i]) {
                S[pos] = e[i] * inv;
                Cc[pos] = (unsigned)(t * 4 + i);
                pos++;
            }
        }
        if (t == 0) g_rcnt[row] = total;
    } else {
        // fully masked row: softmax over uniform -1e9 -> 1/1024 everywhere
        const float u = 1.0f / 1024.0f;
#pragma unroll
        for (int i = 0; i < 4; i++) {
            S[t * 4 + i] = u;
            Cc[t * 4 + i] = (unsigned)(t * 4 + i);
        }
        if (t == 0) g_rcnt[row] = 1024;
    }
}

// ---------------------------------------------------------------------------
// Sparse AV: O[row, h*64+d] = sum_nz p * V[col, d]
// Block = 128 rows of one bh; V staged through smem in 4 chunks of 256 rows.
// One warp owns 16 rows; nz lists are column-sorted.
// ---------------------------------------------------------------------------
__global__ void __launch_bounds__(256) sparse_av() {
    extern __shared__ float Vs[];   // [256][64]
    int bh = blockIdx.y;
    int b = bh / HH, h = bh % HH;
    int t = threadIdx.x;
    int w = t >> 5, lane = t & 31;
    int row0 = blockIdx.x * 128 + w * 16;     // first row for this warp (in bh)
    const float* Vg = g_qkv + (size_t)b * NN * 2304 + 1536 + h * HD;

    float2 acc[16];
    int ptr[16], cnt[16];
#pragma unroll
    for (int r = 0; r < 16; r++) {
        acc[r] = make_float2(0.f, 0.f);
        ptr[r] = 0;
        cnt[r] = g_rcnt[(bh << 10) + row0 + r];
    }

    for (int ch = 0; ch < 4; ch++) {
        __syncthreads();
        // stage V rows [ch*256, ch*256+256) : 4096 float4 by 256 threads
#pragma unroll
        for (int i = 0; i < 16; i++) {
            int idx = t + i * 256;
            int vr = idx >> 4, vc = (idx & 15) * 4;
            *(float4*)&Vs[vr * 64 + vc] =
                *(const float4*)(Vg + (size_t)(ch * 256 + vr) * 2304 + vc);
        }
        __syncthreads();
        int colend = ch * 256 + 256;
        int colbase = ch * 256;
#pragma unroll
        for (int r = 0; r < 16; r++) {
            size_t rowbase = (size_t)((bh << 10) + row0 + r) * NN;
            const float* Pp = g_attn + rowbase;
            const unsigned* Ci = g_cand + rowbase;
            int p = ptr[r], n = cnt[r];
            float2 a = acc[r];
            while (p < n) {
                int c = (int)Ci[p];
                if (c >= colend) break;
                float pv = Pp[p];
                float2 vvl = *(const float2*)&Vs[(c - colbase) * 64 + lane * 2];
                a.x += pv * vvl.x;
                a.y += pv * vvl.y;
                p++;
            }
            acc[r] = a;
            ptr[r] = p;
        }
    }
    // write O
#pragma unroll
    for (int r = 0; r < 16; r++) {
        int n = row0 + r;
        float* Op = g_ao + (size_t)b * NN * DD + (size_t)n * DD + h * HD + lane * 2;
        *(float2*)Op = acc[r];
    }
}

// ---------------------------------------------------------------------------
extern "C" void kernel_launch(void* const* d_in, const int* in_sizes, int n_in,
                              void* d_out, int out_size) {
    const float* x = (const float*)d_in[0];
    const float* W_qkv = (const float*)d_in[1];
    const float* b_qkv = (const float*)d_in[2];
    const float* W_out = (const float*)d_in[3];
    const float* b_out = (const float*)d_in[4];
    float* out = (float*)d_out;

    float* qkv_p; cudaGetSymbolAddress((void**)&qkv_p, g_qkv);
    float* ao_p;  cudaGetSymbolAddress((void**)&ao_p, g_ao);

    static bool attr_set = false;
    if (!attr_set) {
        cudaFuncSetAttribute(sparse_av, cudaFuncAttributeMaxDynamicSharedMemorySize,
                             256 * 64 * 4);
        attr_set = true;
    }

    // 0. zero hist + cand counters
    sel_init<<<BH, 256>>>();
    // 1. QKV projection
    gemm128_bias<<<dim3(2304 / 128, 4096 / 128), 256>>>(x, W_qkv, b_qkv, qkv_p,
                                                        4096, 2304, 768);
    // 2. Scores + fused pass-0 histogram
    gemm_scores<<<dim3(8, 8, BH), 256>>>();
    // 3. Exact kth-smallest threshold
    scan0<<<BH, 256>>>();
    cand_pass<<<dim3(32, BH), 256>>>();
    sel_final<<<BH, 256>>>();
    // 4. Masked softmax + ordered compaction
    softmax_compact<<<BH * NN, 256>>>();
    // 5. Sparse P @ V
    sparse_av<<<dim3(8, BH), 256, 256 * 64 * 4>>>();
    // 6. Output projection
    gemm128_bias<<<dim3(768 / 128, 4096 / 128), 256>>>(ao_p, W_out, b_out, out,
                                                       4096, 768, 768);
}

// round 6
// speedup vs baseline: 1.9803x; 1.9803x over previous
#include <cuda_runtime.h>
#include <cstdint>

#define BB 4
#define NN 1024
#define DD 768
#define HH 12
#define HD 64
#define BH 48
#define KTH 104857

// ---------------- scratch ----------------
__device__ float g_qkv[4096 * 2304];
__device__ float g_attn[(size_t)48 * 1024 * 1024];
__device__ float g_ao[4096 * 768];
__device__ unsigned g_hist[48 * 2048];
__device__ unsigned g_sel[48];
__device__ int g_krem[48];
__device__ float g_thr[48];
__device__ unsigned g_cand[(size_t)48 * 1048576];
__device__ int g_ccnt[48];

__device__ __forceinline__ unsigned fkey(float f) {
    unsigned u = __float_as_uint(f);
    return (u & 0x80000000u) ? ~u : (u ^ 0x80000000u);
}

// ---------------------------------------------------------------------------
// Generic GEMM: C[M,N] = A[M,K] @ B[K,N] + bias[N]  (round-1 proven version)
// ---------------------------------------------------------------------------
__global__ void __launch_bounds__(256) gemm128_bias(
    const float* __restrict__ A, const float* __restrict__ Bm,
    const float* __restrict__ bias, float* __restrict__ C,
    int M, int Nn, int K) {
    __shared__ float As[8][128];
    __shared__ float Bs[8][128];
    int t = threadIdx.x;
    int n0 = blockIdx.x * 128;
    int m0 = blockIdx.y * 128;
    int tx = t & 15, ty = t >> 4;
    float acc[8][8];
#pragma unroll
    for (int i = 0; i < 8; i++)
#pragma unroll
        for (int j = 0; j < 8; j++) acc[i][j] = 0.f;

    int arow = t >> 1, acol = (t & 1) * 4;
    int brow = t >> 5, bcol = (t & 31) * 4;

    for (int k0 = 0; k0 < K; k0 += 8) {
        float4 av = *(const float4*)(A + (size_t)(m0 + arow) * K + k0 + acol);
        As[acol + 0][arow] = av.x;
        As[acol + 1][arow] = av.y;
        As[acol + 2][arow] = av.z;
        As[acol + 3][arow] = av.w;
        float4 bv = *(const float4*)(Bm + (size_t)(k0 + brow) * Nn + n0 + bcol);
        *(float4*)&Bs[brow][bcol] = bv;
        __syncthreads();
#pragma unroll
        for (int kk = 0; kk < 8; kk++) {
            float a[8], b[8];
#pragma unroll
            for (int i = 0; i < 8; i++) a[i] = As[kk][ty * 8 + i];
#pragma unroll
            for (int j = 0; j < 8; j++) b[j] = Bs[kk][tx * 8 + j];
#pragma unroll
            for (int i = 0; i < 8; i++)
#pragma unroll
                for (int j = 0; j < 8; j++) acc[i][j] += a[i] * b[j];
        }
        __syncthreads();
    }
    float bb[8];
#pragma unroll
    for (int j = 0; j < 8; j++) bb[j] = bias[n0 + tx * 8 + j];
#pragma unroll
    for (int i = 0; i < 8; i++) {
        int row = m0 + ty * 8 + i;
#pragma unroll
        for (int j0 = 0; j0 < 8; j0 += 4) {
            float4 v;
            v.x = acc[i][j0 + 0] + bb[j0 + 0];
            v.y = acc[i][j0 + 1] + bb[j0 + 1];
            v.z = acc[i][j0 + 2] + bb[j0 + 2];
            v.w = acc[i][j0 + 3] + bb[j0 + 3];
            *(float4*)(C + (size_t)row * Nn + n0 + tx * 8 + j0) = v;
        }
    }
}

// ---------------------------------------------------------------------------
// Scores: S[bh][n][m] = 0.125 * sum_d Q[n,d] K[m,d]  + fused pass-0 histogram
// ---------------------------------------------------------------------------
__global__ void __launch_bounds__(256) gemm_scores() {
    __shared__ float Qs[8][128];
    __shared__ float Ks[8][128];
    __shared__ unsigned hsm[2048];
    int bh = blockIdx.z;
    int b = bh / HH, h = bh % HH;
    const float* Q = g_qkv + (size_t)b * NN * 2304 + h * HD;
    const float* Kp = g_qkv + (size_t)b * NN * 2304 + 768 + h * HD;
    float* S = g_attn + (size_t)bh * NN * NN;

    int t = threadIdx.x;
    int m0 = blockIdx.x * 128;
    int n0 = blockIdx.y * 128;
    int tx = t & 15, ty = t >> 4;
    for (int j = t; j < 2048; j += 256) hsm[j] = 0u;
    float acc[8][8];
#pragma unroll
    for (int i = 0; i < 8; i++)
#pragma unroll
        for (int j = 0; j < 8; j++) acc[i][j] = 0.f;

    int r = t >> 1, c4 = (t & 1) * 4;

    for (int d0 = 0; d0 < HD; d0 += 8) {
        float4 qv = *(const float4*)(Q + (size_t)(n0 + r) * 2304 + d0 + c4);
        Qs[c4 + 0][r] = qv.x; Qs[c4 + 1][r] = qv.y;
        Qs[c4 + 2][r] = qv.z; Qs[c4 + 3][r] = qv.w;
        float4 kv = *(const float4*)(Kp + (size_t)(m0 + r) * 2304 + d0 + c4);
        Ks[c4 + 0][r] = kv.x; Ks[c4 + 1][r] = kv.y;
        Ks[c4 + 2][r] = kv.z; Ks[c4 + 3][r] = kv.w;
        __syncthreads();
#pragma unroll
        for (int kk = 0; kk < 8; kk++) {
            float a[8], bvv[8];
#pragma unroll
            for (int i = 0; i < 8; i++) a[i] = Qs[kk][ty * 8 + i];
#pragma unroll
            for (int j = 0; j < 8; j++) bvv[j] = Ks[kk][tx * 8 + j];
#pragma unroll
            for (int i = 0; i < 8; i++)
#pragma unroll
                for (int j = 0; j < 8; j++) acc[i][j] += a[i] * bvv[j];
        }
        __syncthreads();
    }
#pragma unroll
    for (int i = 0; i < 8; i++) {
        int row = n0 + ty * 8 + i;
#pragma unroll
        for (int j0 = 0; j0 < 8; j0 += 4) {
            float4 v;
            v.x = acc[i][j0 + 0] * 0.125f;
            v.y = acc[i][j0 + 1] * 0.125f;
            v.z = acc[i][j0 + 2] * 0.125f;
            v.w = acc[i][j0 + 3] * 0.125f;
            atomicAdd(&hsm[fkey(v.x) >> 21], 1u);
            atomicAdd(&hsm[fkey(v.y) >> 21], 1u);
            atomicAdd(&hsm[fkey(v.z) >> 21], 1u);
            atomicAdd(&hsm[fkey(v.w) >> 21], 1u);
            *(float4*)(S + (size_t)row * NN + m0 + tx * 8 + j0) = v;
        }
    }
    __syncthreads();
    unsigned* gh = g_hist + bh * 2048;
    for (int j = t; j < 2048; j += 256) {
        unsigned c = hsm[j];
        if (c) atomicAdd(&gh[j], c);
    }
}

// ---------------------------------------------------------------------------
// Selection: init -> scan -> candidate gather -> final select
// ---------------------------------------------------------------------------
__global__ void sel_init() {
    int bh = blockIdx.x, t = threadIdx.x;
    for (int j = t; j < 2048; j += 256) g_hist[bh * 2048 + j] = 0u;
    if (t == 0) g_ccnt[bh] = 0;
}

__global__ void scan0() {
    int bh = blockIdx.x, t = threadIdx.x;
    __shared__ unsigned ssum[256];
    __shared__ int s_sel;
    __shared__ unsigned s_kin;
    const unsigned* hist = g_hist + bh * 2048;
    unsigned loc[8], lsum = 0;
#pragma unroll
    for (int i = 0; i < 8; i++) { loc[i] = hist[t * 8 + i]; lsum += loc[i]; }
    ssum[t] = lsum;
    __syncthreads();
    if (t == 0) {
        unsigned k = KTH, cum = 0, kin = k;
        int sel = 255;
        for (int i = 0; i < 256; i++) {
            if (cum + ssum[i] >= k) { sel = i; kin = k - cum; break; }
            cum += ssum[i];
        }
        s_sel = sel; s_kin = kin;
    }
    __syncthreads();
    if (t == s_sel) {
        unsigned kk = s_kin, cum = 0, d = t * 8 + 7, knew = kk;
#pragma unroll
        for (int i = 0; i < 8; i++) {
            if (cum + loc[i] >= kk) { d = t * 8 + i; knew = kk - cum; break; }
            cum += loc[i];
        }
        g_sel[bh] = d;
        g_krem[bh] = (int)knew;
    }
}

__device__ __forceinline__ void push_cand(unsigned key, unsigned sel, unsigned* cand,
                                          int* cnt, unsigned lane) {
    bool m = (key >> 21) == sel;
    unsigned bal = __ballot_sync(0xffffffffu, m);
    if (bal) {
        int leader = __ffs(bal) - 1;
        int base = 0;
        if ((int)lane == leader) base = atomicAdd(cnt, __popc(bal));
        base = __shfl_sync(0xffffffffu, base, leader);
        if (m) cand[base + __popc(bal & ((1u << lane) - 1u))] = key;
    }
}

__global__ void cand_pass() {
    int bh = blockIdx.y, t = threadIdx.x;
    unsigned lane = t & 31;
    unsigned sel = g_sel[bh];
    unsigned* cand = g_cand + (size_t)bh * 1048576;
    int* cnt = &g_ccnt[bh];
    const float4* Sp = (const float4*)(g_attn + (size_t)bh * 1048576) +
                       (size_t)blockIdx.x * 8192;
    for (int i = 0; i < 32; i++) {
        float4 v = Sp[i * 256 + t];
        push_cand(fkey(v.x), sel, cand, cnt, lane);
        push_cand(fkey(v.y), sel, cand, cnt, lane);
        push_cand(fkey(v.z), sel, cand, cnt, lane);
        push_cand(fkey(v.w), sel, cand, cnt, lane);
    }
}

__global__ void sel_final() {
    int bh = blockIdx.x, t = threadIdx.x;
    __shared__ unsigned sh[2048];
    __shared__ unsigned ssum[256];
    __shared__ int s_sel;
    __shared__ unsigned s_kin;
    __shared__ unsigned s_b1, s_k2;
    int cnt = g_ccnt[bh];
    const unsigned* cand = g_cand + (size_t)bh * 1048576;

    // pass A: bits 20..10
    for (int j = t; j < 2048; j += 256) sh[j] = 0u;
    __syncthreads();
    for (int i = t; i < cnt; i += 256) atomicAdd(&sh[(cand[i] >> 10) & 2047u], 1u);
    __syncthreads();
    {
        unsigned loc[8], lsum = 0;
#pragma unroll
        for (int i = 0; i < 8; i++) { loc[i] = sh[t * 8 + i]; lsum += loc[i]; }
        ssum[t] = lsum;
        __syncthreads();
        if (t == 0) {
            unsigned k = (unsigned)g_krem[bh], cum = 0, kin = k;
            int sel = 255;
            for (int i = 0; i < 256; i++) {
                if (cum + ssum[i] >= k) { sel = i; kin = k - cum; break; }
                cum += ssum[i];
            }
            s_sel = sel; s_kin = kin;
        }
        __syncthreads();
        if (t == s_sel) {
            unsigned kk = s_kin, cum = 0, d = t * 8 + 7, knew = kk;
#pragma unroll
            for (int i = 0; i < 8; i++) {
                if (cum + loc[i] >= kk) { d = t * 8 + i; knew = kk - cum; break; }
                cum += loc[i];
            }
            s_b1 = d; s_k2 = knew;
        }
        __syncthreads();
    }
    unsigned b1 = s_b1;
    __syncthreads();

    // pass B: bits 9..0
    for (int j = t; j < 1024; j += 256) sh[j] = 0u;
    __syncthreads();
    for (int i = t; i < cnt; i += 256) {
        unsigned ky = cand[i];
        if (((ky >> 10) & 2047u) == b1) atomicAdd(&sh[ky & 1023u], 1u);
    }
    __syncthreads();
    {
        unsigned loc[4], lsum = 0;
#pragma unroll
        for (int i = 0; i < 4; i++) { loc[i] = sh[t * 4 + i]; lsum += loc[i]; }
        ssum[t] = lsum;
        __syncthreads();
        if (t == 0) {
            unsigned k = s_k2, cum = 0, kin = k;
            int sel = 255;
            for (int i = 0; i < 256; i++) {
                if (cum + ssum[i] >= k) { sel = i; kin = k - cum; break; }
                cum += ssum[i];
            }
            s_sel = sel; s_kin = kin;
        }
        __syncthreads();
        if (t == s_sel) {
            unsigned kk = s_kin, cum = 0, d = t * 4 + 3;
#pragma unroll
            for (int i = 0; i < 4; i++) {
                if (cum + loc[i] >= kk) { d = t * 4 + i; break; }
                cum += loc[i];
            }
            unsigned key = (g_sel[bh] << 21) | (b1 << 10) | d;
            unsigned bits = (key & 0x80000000u) ? (key ^ 0x80000000u) : ~key;
            g_thr[bh] = __uint_as_float(bits);
        }
    }
}

// ---------------------------------------------------------------------------
// Masked softmax (float4, one block per row, in place)
// ---------------------------------------------------------------------------
__global__ void softmax_mask() {
    int row = blockIdx.x, bh = row >> 10;
    float thr = g_thr[bh];
    float4* S = (float4*)(g_attn + (size_t)row * NN);
    int t = threadIdx.x;
    unsigned lane = t & 31, w = t >> 5;
    __shared__ float red[8];

    float4 vv = S[t];
    float v[4] = {vv.x, vv.y, vv.z, vv.w};
    float mx = -3.0e38f;
#pragma unroll
    for (int i = 0; i < 4; i++) {
        v[i] = (v[i] <= thr) ? -1e9f : v[i];
        mx = fmaxf(mx, v[i]);
    }
#pragma unroll
    for (int o = 16; o; o >>= 1) mx = fmaxf(mx, __shfl_xor_sync(0xffffffffu, mx, o));
    if (lane == 0) red[w] = mx;
    __syncthreads();
    float m = red[0];
#pragma unroll
    for (int i = 1; i < 8; i++) m = fmaxf(m, red[i]);

    float e[4], s = 0.f;
#pragma unroll
    for (int i = 0; i < 4; i++) { e[i] = __expf(v[i] - m); s += e[i]; }
#pragma unroll
    for (int o = 16; o; o >>= 1) s += __shfl_xor_sync(0xffffffffu, s, o);
    __syncthreads();
    if (lane == 0) red[w] = s;
    __syncthreads();
    float tot = 0.f;
#pragma unroll
    for (int i = 0; i < 8; i++) tot += red[i];
    float inv = 1.f / tot;
    float4 ov = {e[0] * inv, e[1] * inv, e[2] * inv, e[3] * inv};
    S[t] = ov;
}

// ---------------------------------------------------------------------------
// AV: O[b,n,h*64+j] = sum_m P[bh][n][m] V[b,m,h,j];  128x64x8 tile (round-1)
// ---------------------------------------------------------------------------
__global__ void __launch_bounds__(256) gemm_av() {
    int bh = blockIdx.z;
    int b = bh / HH, h = bh % HH;
    const float* P = g_attn + (size_t)bh * NN * NN;
    const float* V = g_qkv + (size_t)b * NN * 2304 + 1536 + h * HD;
    float* O = g_ao + (size_t)b * NN * DD + h * HD;

    __shared__ float As[8][128];
    __shared__ float Bs[8][64];
    int t = threadIdx.x;
    int m0 = blockIdx.y * 128;
    int tx = t & 15, ty = t >> 4;
    float acc[8][4];
#pragma unroll
    for (int i = 0; i < 8; i++)
#pragma unroll
        for (int j = 0; j < 4; j++) acc[i][j] = 0.f;

    int arow = t >> 1, acol = (t & 1) * 4;

    for (int k0 = 0; k0 < NN; k0 += 8) {
        float4 av = *(const float4*)(P + (size_t)(m0 + arow) * NN + k0 + acol);
        As[acol + 0][arow] = av.x;
        As[acol + 1][arow] = av.y;
        As[acol + 2][arow] = av.z;
        As[acol + 3][arow] = av.w;
        if (t < 128) {
            int brow = t >> 4, bcol = (t & 15) * 4;
            float4 bv = *(const float4*)(V + (size_t)(k0 + brow) * 2304 + bcol);
            *(float4*)&Bs[brow][bcol] = bv;
        }
        __syncthreads();
#pragma unroll
        for (int kk = 0; kk < 8; kk++) {
            float a[8], bvv[4];
#pragma unroll
            for (int i = 0; i < 8; i++) a[i] = As[kk][ty * 8 + i];
#pragma unroll
            for (int j = 0; j < 4; j++) bvv[j] = Bs[kk][tx * 4 + j];
#pragma unroll
            for (int i = 0; i < 8; i++)
#pragma unroll
                for (int j = 0; j < 4; j++) acc[i][j] += a[i] * bvv[j];
        }
        __syncthreads();
    }
#pragma unroll
    for (int i = 0; i < 8; i++) {
        int row = m0 + ty * 8 + i;
        float4 v;
        v.x = acc[i][0]; v.y = acc[i][1]; v.z = acc[i][2]; v.w = acc[i][3];
        *(float4*)(O + (size_t)row * DD + tx * 4) = v;
    }
}

// ---------------------------------------------------------------------------
extern "C" void kernel_launch(void* const* d_in, const int* in_sizes, int n_in,
                              void* d_out, int out_size) {
    const float* x = (const float*)d_in[0];
    const float* W_qkv = (const float*)d_in[1];
    const float* b_qkv = (const float*)d_in[2];
    const float* W_out = (const float*)d_in[3];
    const float* b_out = (const float*)d_in[4];
    float* out = (float*)d_out;

    float* qkv_p; cudaGetSymbolAddress((void**)&qkv_p, g_qkv);
    float* ao_p;  cudaGetSymbolAddress((void**)&ao_p, g_ao);

    // 0. zero hist + cand counters
    sel_init<<<BH, 256>>>();
    // 1. QKV projection
    gemm128_bias<<<dim3(2304 / 128, 4096 / 128), 256>>>(x, W_qkv, b_qkv, qkv_p,
                                                        4096, 2304, 768);
    // 2. Scores + fused pass-0 histogram
    gemm_scores<<<dim3(8, 8, BH), 256>>>();
    // 3. Exact kth-smallest threshold
    scan0<<<BH, 256>>>();
    cand_pass<<<dim3(32, BH), 256>>>();
    sel_final<<<BH, 256>>>();
    // 4. Masked softmax in place
    softmax_mask<<<BH * NN, 256>>>();
    // 5. P @ V (dense, round-1)
    gemm_av<<<dim3(1, 8, BH), 256>>>();
    // 6. Output projection
    gemm128_bias<<<dim3(768 / 128, 4096 / 128), 256>>>(ao_p, W_out, b_out, out,
                                                       4096, 768, 768);
}

// round 7
// speedup vs baseline: 3.0591x; 1.5448x over previous
#include <cuda_runtime.h>
#include <cstdint>

#define BB 4
#define NN 1024
#define DD 768
#define HH 12
#define HD 64
#define BH 48
#define KTH 104857

// ---------------- scratch ----------------
__device__ float g_qkv[4096 * 2304];
__device__ float g_attn[(size_t)48 * 1024 * 1024];
__device__ float g_ao[4096 * 768];
__device__ unsigned g_hist[48 * 2048];
__device__ unsigned g_sel[48];
__device__ int g_krem[48];
__device__ float g_thr[48];
__device__ unsigned g_cand[(size_t)48 * 1048576];
__device__ int g_ccnt[48];

__device__ __forceinline__ unsigned fkey(float f) {
    unsigned u = __float_as_uint(f);
    return (u & 0x80000000u) ? ~u : (u ^ 0x80000000u);
}

// ---------------------------------------------------------------------------
// Generic GEMM: C[M,N] = A[M,K] @ B[K,N] + bias[N]   (round-1 EXACT)
// ---------------------------------------------------------------------------
__global__ void gemm128_bias(const float* __restrict__ A, const float* __restrict__ Bm,
                             const float* __restrict__ bias, float* __restrict__ C,
                             int M, int Nn, int K) {
    __shared__ float As[8][128];
    __shared__ float Bs[8][128];
    int t = threadIdx.x;
    int n0 = blockIdx.x * 128;
    int m0 = blockIdx.y * 128;
    int tx = t & 15, ty = t >> 4;
    float acc[8][8];
#pragma unroll
    for (int i = 0; i < 8; i++)
#pragma unroll
        for (int j = 0; j < 8; j++) acc[i][j] = 0.f;

    int arow = t >> 1, acol = (t & 1) * 4;
    int brow = t >> 5, bcol = (t & 31) * 4;

    for (int k0 = 0; k0 < K; k0 += 8) {
        float4 av = *(const float4*)(A + (size_t)(m0 + arow) * K + k0 + acol);
        As[acol + 0][arow] = av.x;
        As[acol + 1][arow] = av.y;
        As[acol + 2][arow] = av.z;
        As[acol + 3][arow] = av.w;
        float4 bv = *(const float4*)(Bm + (size_t)(k0 + brow) * Nn + n0 + bcol);
        *(float4*)&Bs[brow][bcol] = bv;
        __syncthreads();
#pragma unroll
        for (int kk = 0; kk < 8; kk++) {
            float a[8], b[8];
#pragma unroll
            for (int i = 0; i < 8; i++) a[i] = As[kk][ty * 8 + i];
#pragma unroll
            for (int j = 0; j < 8; j++) b[j] = Bs[kk][tx * 8 + j];
#pragma unroll
            for (int i = 0; i < 8; i++)
#pragma unroll
                for (int j = 0; j < 8; j++) acc[i][j] += a[i] * b[j];
        }
        __syncthreads();
    }
    float bb[8];
#pragma unroll
    for (int j = 0; j < 8; j++) bb[j] = bias[n0 + tx * 8 + j];
#pragma unroll
    for (int i = 0; i < 8; i++) {
        int row = m0 + ty * 8 + i;
#pragma unroll
        for (int j0 = 0; j0 < 8; j0 += 4) {
            float4 v;
            v.x = acc[i][j0 + 0] + bb[j0 + 0];
            v.y = acc[i][j0 + 1] + bb[j0 + 1];
            v.z = acc[i][j0 + 2] + bb[j0 + 2];
            v.w = acc[i][j0 + 3] + bb[j0 + 3];
            *(float4*)(C + (size_t)row * Nn + n0 + tx * 8 + j0) = v;
        }
    }
}

// ---------------------------------------------------------------------------
// Scores: S[bh][n][m] = 0.125 * sum_d Q[n,d] K[m,d]   (round-1 EXACT, no hist)
// ---------------------------------------------------------------------------
__global__ void gemm_scores() {
    int bh = blockIdx.z;
    int b = bh / HH, h = bh % HH;
    const float* Q = g_qkv + (size_t)b * NN * 2304 + h * HD;
    const float* Kp = g_qkv + (size_t)b * NN * 2304 + 768 + h * HD;
    float* S = g_attn + (size_t)bh * NN * NN;

    __shared__ float Qs[8][128];
    __shared__ float Ks[8][128];
    int t = threadIdx.x;
    int m0 = blockIdx.x * 128;
    int n0 = blockIdx.y * 128;
    int tx = t & 15, ty = t >> 4;
    float acc[8][8];
#pragma unroll
    for (int i = 0; i < 8; i++)
#pragma unroll
        for (int j = 0; j < 8; j++) acc[i][j] = 0.f;

    int r = t >> 1, c4 = (t & 1) * 4;

    for (int d0 = 0; d0 < HD; d0 += 8) {
        float4 qv = *(const float4*)(Q + (size_t)(n0 + r) * 2304 + d0 + c4);
        Qs[c4 + 0][r] = qv.x; Qs[c4 + 1][r] = qv.y;
        Qs[c4 + 2][r] = qv.z; Qs[c4 + 3][r] = qv.w;
        float4 kv = *(const float4*)(Kp + (size_t)(m0 + r) * 2304 + d0 + c4);
        Ks[c4 + 0][r] = kv.x; Ks[c4 + 1][r] = kv.y;
        Ks[c4 + 2][r] = kv.z; Ks[c4 + 3][r] = kv.w;
        __syncthreads();
#pragma unroll
        for (int kk = 0; kk < 8; kk++) {
            float a[8], bvv[8];
#pragma unroll
            for (int i = 0; i < 8; i++) a[i] = Qs[kk][ty * 8 + i];
#pragma unroll
            for (int j = 0; j < 8; j++) bvv[j] = Ks[kk][tx * 8 + j];
#pragma unroll
            for (int i = 0; i < 8; i++)
#pragma unroll
                for (int j = 0; j < 8; j++) acc[i][j] += a[i] * bvv[j];
        }
        __syncthreads();
    }
#pragma unroll
    for (int i = 0; i < 8; i++) {
        int row = n0 + ty * 8 + i;
#pragma unroll
        for (int j0 = 0; j0 < 8; j0 += 4) {
            float4 v;
            v.x = acc[i][j0 + 0] * 0.125f;
            v.y = acc[i][j0 + 1] * 0.125f;
            v.z = acc[i][j0 + 2] * 0.125f;
            v.w = acc[i][j0 + 3] * 0.125f;
            *(float4*)(S + (size_t)row * NN + m0 + tx * 8 + j0) = v;
        }
    }
}

// ---------------------------------------------------------------------------
// Selection (round-2 EXACT): init -> hist0 -> scan0 -> cand gather -> final
// ---------------------------------------------------------------------------
__global__ void sel_init() {
    int bh = blockIdx.x, t = threadIdx.x;
    for (int j = t; j < 2048; j += 256) g_hist[bh * 2048 + j] = 0u;
    if (t == 0) g_ccnt[bh] = 0;
}

__global__ void hist0() {
    int bh = blockIdx.y, t = threadIdx.x;
    __shared__ unsigned sh[2048];
    for (int j = t; j < 2048; j += 256) sh[j] = 0u;
    __syncthreads();
    const float4* Sp = (const float4*)(g_attn + (size_t)bh * 1048576) +
                       (size_t)blockIdx.x * 8192;
    for (int i = 0; i < 32; i++) {
        float4 v = Sp[i * 256 + t];
        atomicAdd(&sh[fkey(v.x) >> 21], 1u);
        atomicAdd(&sh[fkey(v.y) >> 21], 1u);
        atomicAdd(&sh[fkey(v.z) >> 21], 1u);
        atomicAdd(&sh[fkey(v.w) >> 21], 1u);
    }
    __syncthreads();
    for (int j = t; j < 2048; j += 256) {
        unsigned cc = sh[j];
        if (cc) atomicAdd(&g_hist[bh * 2048 + j], cc);
    }
}

__global__ void scan0() {
    int bh = blockIdx.x, t = threadIdx.x;
    __shared__ unsigned ssum[256];
    __shared__ int s_sel;
    __shared__ unsigned s_kin;
    const unsigned* hist = g_hist + bh * 2048;
    unsigned loc[8], lsum = 0;
#pragma unroll
    for (int i = 0; i < 8; i++) { loc[i] = hist[t * 8 + i]; lsum += loc[i]; }
    ssum[t] = lsum;
    __syncthreads();
    if (t == 0) {
        unsigned k = KTH, cum = 0, kin = k;
        int sel = 255;
        for (int i = 0; i < 256; i++) {
            if (cum + ssum[i] >= k) { sel = i; kin = k - cum; break; }
            cum += ssum[i];
        }
        s_sel = sel; s_kin = kin;
    }
    __syncthreads();
    if (t == s_sel) {
        unsigned kk = s_kin, cum = 0, d = t * 8 + 7, knew = kk;
#pragma unroll
        for (int i = 0; i < 8; i++) {
            if (cum + loc[i] >= kk) { d = t * 8 + i; knew = kk - cum; break; }
            cum += loc[i];
        }
        g_sel[bh] = d;
        g_krem[bh] = (int)knew;
    }
}

__device__ __forceinline__ void push_cand(unsigned key, unsigned sel, unsigned* cand,
                                          int* cnt, unsigned lane) {
    bool m = (key >> 21) == sel;
    unsigned bal = __ballot_sync(0xffffffffu, m);
    if (bal) {
        int leader = __ffs(bal) - 1;
        int base = 0;
        if ((int)lane == leader) base = atomicAdd(cnt, __popc(bal));
        base = __shfl_sync(0xffffffffu, base, leader);
        if (m) cand[base + __popc(bal & ((1u << lane) - 1u))] = key;
    }
}

__global__ void cand_pass() {
    int bh = blockIdx.y, t = threadIdx.x;
    unsigned lane = t & 31;
    unsigned sel = g_sel[bh];
    unsigned* cand = g_cand + (size_t)bh * 1048576;
    int* cnt = &g_ccnt[bh];
    const float4* Sp = (const float4*)(g_attn + (size_t)bh * 1048576) +
                       (size_t)blockIdx.x * 8192;
    for (int i = 0; i < 32; i++) {
        float4 v = Sp[i * 256 + t];
        push_cand(fkey(v.x), sel, cand, cnt, lane);
        push_cand(fkey(v.y), sel, cand, cnt, lane);
        push_cand(fkey(v.z), sel, cand, cnt, lane);
        push_cand(fkey(v.w), sel, cand, cnt, lane);
    }
}

__global__ void sel_final() {
    int bh = blockIdx.x, t = threadIdx.x;
    __shared__ unsigned sh[2048];
    __shared__ unsigned ssum[256];
    __shared__ int s_sel;
    __shared__ unsigned s_kin;
    __shared__ unsigned s_b1, s_k2;
    int cnt = g_ccnt[bh];
    const unsigned* cand = g_cand + (size_t)bh * 1048576;

    // pass A: bits 20..10
    for (int j = t; j < 2048; j += 256) sh[j] = 0u;
    __syncthreads();
    for (int i = t; i < cnt; i += 256) atomicAdd(&sh[(cand[i] >> 10) & 2047u], 1u);
    __syncthreads();
    {
        unsigned loc[8], lsum = 0;
#pragma unroll
        for (int i = 0; i < 8; i++) { loc[i] = sh[t * 8 + i]; lsum += loc[i]; }
        ssum[t] = lsum;
        __syncthreads();
        if (t == 0) {
            unsigned k = (unsigned)g_krem[bh], cum = 0, kin = k;
            int sel = 255;
            for (int i = 0; i < 256; i++) {
                if (cum + ssum[i] >= k) { sel = i; kin = k - cum; break; }
                cum += ssum[i];
            }
            s_sel = sel; s_kin = kin;
        }
        __syncthreads();
        if (t == s_sel) {
            unsigned kk = s_kin, cum = 0, d = t * 8 + 7, knew = kk;
#pragma unroll
            for (int i = 0; i < 8; i++) {
                if (cum + loc[i] >= kk) { d = t * 8 + i; knew = kk - cum; break; }
                cum += loc[i];
            }
            s_b1 = d; s_k2 = knew;
        }
        __syncthreads();
    }
    unsigned b1 = s_b1;
    __syncthreads();

    // pass B: bits 9..0
    for (int j = t; j < 1024; j += 256) sh[j] = 0u;
    __syncthreads();
    for (int i = t; i < cnt; i += 256) {
        unsigned ky = cand[i];
        if (((ky >> 10) & 2047u) == b1) atomicAdd(&sh[ky & 1023u], 1u);
    }
    __syncthreads();
    {
        unsigned loc[4], lsum = 0;
#pragma unroll
        for (int i = 0; i < 4; i++) { loc[i] = sh[t * 4 + i]; lsum += loc[i]; }
        ssum[t] = lsum;
        __syncthreads();
        if (t == 0) {
            unsigned k = s_k2, cum = 0, kin = k;
            int sel = 255;
            for (int i = 0; i < 256; i++) {
                if (cum + ssum[i] >= k) { sel = i; kin = k - cum; break; }
                cum += ssum[i];
            }
            s_sel = sel; s_kin = kin;
        }
        __syncthreads();
        if (t == s_sel) {
            unsigned kk = s_kin, cum = 0, d = t * 4 + 3;
#pragma unroll
            for (int i = 0; i < 4; i++) {
                if (cum + loc[i] >= kk) { d = t * 4 + i; break; }
                cum += loc[i];
            }
            unsigned key = (g_sel[bh] << 21) | (b1 << 10) | d;
            unsigned bits = (key & 0x80000000u) ? (key ^ 0x80000000u) : ~key;
            g_thr[bh] = __uint_as_float(bits);
        }
    }
}

// ---------------------------------------------------------------------------
// Masked softmax (float4 loads, one block per row, in place)
// ---------------------------------------------------------------------------
__global__ void softmax_mask() {
    int row = blockIdx.x, bh = row >> 10;
    float thr = g_thr[bh];
    float4* S = (float4*)(g_attn + (size_t)row * NN);
    int t = threadIdx.x;
    unsigned lane = t & 31, w = t >> 5;
    __shared__ float red[8];

    float4 vv = S[t];
    float v[4] = {vv.x, vv.y, vv.z, vv.w};
    float mx = -3.0e38f;
#pragma unroll
    for (int i = 0; i < 4; i++) {
        v[i] = (v[i] <= thr) ? -1e9f : v[i];
        mx = fmaxf(mx, v[i]);
    }
#pragma unroll
    for (int o = 16; o; o >>= 1) mx = fmaxf(mx, __shfl_xor_sync(0xffffffffu, mx, o));
    if (lane == 0) red[w] = mx;
    __syncthreads();
    float m = red[0];
#pragma unroll
    for (int i = 1; i < 8; i++) m = fmaxf(m, red[i]);

    float e[4], s = 0.f;
#pragma unroll
    for (int i = 0; i < 4; i++) { e[i] = __expf(v[i] - m); s += e[i]; }
#pragma unroll
    for (int o = 16; o; o >>= 1) s += __shfl_xor_sync(0xffffffffu, s, o);
    __syncthreads();
    if (lane == 0) red[w] = s;
    __syncthreads();
    float tot = 0.f;
#pragma unroll
    for (int i = 0; i < 8; i++) tot += red[i];
    float inv = 1.f / tot;
    float4 ov = {e[0] * inv, e[1] * inv, e[2] * inv, e[3] * inv};
    S[t] = ov;
}

// ---------------------------------------------------------------------------
// AV: O[b,n,h*64+j] = sum_m P[bh][n][m] V[b,m,h,j]   (round-1 EXACT)
// ---------------------------------------------------------------------------
__global__ void gemm_av() {
    int bh = blockIdx.z;
    int b = bh / HH, h = bh % HH;
    const float* P = g_attn + (size_t)bh * NN * NN;
    const float* V = g_qkv + (size_t)b * NN * 2304 + 1536 + h * HD;
    float* O = g_ao + (size_t)b * NN * DD + h * HD;

    __shared__ float As[8][128];
    __shared__ float Bs[8][64];
    int t = threadIdx.x;
    int m0 = blockIdx.y * 128;
    int tx = t & 15, ty = t >> 4;
    float acc[8][4];
#pragma unroll
    for (int i = 0; i < 8; i++)
#pragma unroll
        for (int j = 0; j < 4; j++) acc[i][j] = 0.f;

    int arow = t >> 1, acol = (t & 1) * 4;

    for (int k0 = 0; k0 < NN; k0 += 8) {
        float4 av = *(const float4*)(P + (size_t)(m0 + arow) * NN + k0 + acol);
        As[acol + 0][arow] = av.x;
        As[acol + 1][arow] = av.y;
        As[acol + 2][arow] = av.z;
        As[acol + 3][arow] = av.w;
        if (t < 128) {
            int brow = t >> 4, bcol = (t & 15) * 4;
            float4 bv = *(const float4*)(V + (size_t)(k0 + brow) * 2304 + bcol);
            *(float4*)&Bs[brow][bcol] = bv;
        }
        __syncthreads();
#pragma unroll
        for (int kk = 0; kk < 8; kk++) {
            float a[8], bvv[4];
#pragma unroll
            for (int i = 0; i < 8; i++) a[i] = As[kk][ty * 8 + i];
#pragma unroll
            for (int j = 0; j < 4; j++) bvv[j] = Bs[kk][tx * 4 + j];
#pragma unroll
            for (int i = 0; i < 8; i++)
#pragma unroll
                for (int j = 0; j < 4; j++) acc[i][j] += a[i] * bvv[j];
        }
        __syncthreads();
    }
#pragma unroll
    for (int i = 0; i < 8; i++) {
        int row = m0 + ty * 8 + i;
        float4 v;
        v.x = acc[i][0]; v.y = acc[i][1]; v.z = acc[i][2]; v.w = acc[i][3];
        *(float4*)(O + (size_t)row * DD + tx * 4) = v;
    }
}

// ---------------------------------------------------------------------------
extern "C" void kernel_launch(void* const* d_in, const int* in_sizes, int n_in,
                              void* d_out, int out_size) {
    const float* x = (const float*)d_in[0];
    const float* W_qkv = (const float*)d_in[1];
    const float* b_qkv = (const float*)d_in[2];
    const float* W_out = (const float*)d_in[3];
    const float* b_out = (const float*)d_in[4];
    float* out = (float*)d_out;

    float* qkv_p; cudaGetSymbolAddress((void**)&qkv_p, g_qkv);
    float* ao_p;  cudaGetSymbolAddress((void**)&ao_p, g_ao);

    // 0. zero hist + cand counters
    sel_init<<<BH, 256>>>();
    // 1. QKV projection
    gemm128_bias<<<dim3(2304 / 128, 4096 / 128), 256>>>(x, W_qkv, b_qkv, qkv_p,
                                                        4096, 2304, 768);
    // 2. Scores (plain, round-1)
    gemm_scores<<<dim3(8, 8, BH), 256>>>();
    // 3. Threshold: pass-0 hist + scan + candidate gather + final select
    hist0<<<dim3(32, BH), 256>>>();
    scan0<<<BH, 256>>>();
    cand_pass<<<dim3(32, BH), 256>>>();
    sel_final<<<BH, 256>>>();
    // 4. Masked softmax in place
    softmax_mask<<<BH * NN, 256>>>();
    // 5. P @ V
    gemm_av<<<dim3(1, 8, BH), 256>>>();
    // 6. Output projection
    gemm128_bias<<<dim3(768 / 128, 4096 / 128), 256>>>(ao_p, W_out, b_out, out,
                                                       4096, 768, 768);
}

// round 8
// speedup vs baseline: 6.0900x; 1.9908x over previous
#include <cuda_runtime.h>
#include <cuda_bf16.h>
#include <cstdint>

#define BB 4
#define NN 1024
#define DD 768
#define HH 12
#define HD 64
#define BH 48
#define KTH 104857

// ---------------- scratch ----------------
__device__ float g_qkv[4096 * 2304];
__device__ float g_attn[(size_t)48 * 1024 * 1024];
__device__ float g_ao[4096 * 768];
__device__ unsigned g_hist[48 * 2048];
__device__ unsigned g_sel[48];
__device__ int g_krem[48];
__device__ float g_thr[48];
__device__ unsigned g_cand[(size_t)48 * 1048576];
__device__ int g_bcnt[48 * 32];

__device__ __forceinline__ unsigned fkey(float f) {
    unsigned u = __float_as_uint(f);
    return (u & 0x80000000u) ? ~u : (u ^ 0x80000000u);
}

// ---------------- bf16 mma helpers ----------------
__device__ __forceinline__ void mma_bf16(float* c, unsigned a0, unsigned a1,
                                         unsigned a2, unsigned a3,
                                         unsigned b0, unsigned b1) {
    asm volatile(
        "mma.sync.aligned.m16n8k16.row.col.f32.bf16.bf16.f32 "
        "{%0,%1,%2,%3}, {%4,%5,%6,%7}, {%8,%9}, {%0,%1,%2,%3};"
        : "+f"(c[0]), "+f"(c[1]), "+f"(c[2]), "+f"(c[3])
        : "r"(a0), "r"(a1), "r"(a2), "r"(a3), "r"(b0), "r"(b1));
}

// ---------------------------------------------------------------------------
// Split-bf16 tensor-core GEMM.
// C[m,n] = scale * sum_k A[m,k]*Bop[k,n] (+bias)
// A: [M][K] k-contig. If TRANSB: B global is [K][N] n-contig (weights / V).
// Else: B global is [N][K] k-contig (scores: the K matrix). NT = N block tile.
// Block tile 128 x NT, BK=16, 256 threads (8 warps of 64 x NT/4).
// ---------------------------------------------------------------------------
template <int NT, bool TRANSB, bool BIAS, bool SCALE>
__global__ void __launch_bounds__(256) mma_gemm(
    const float* __restrict__ A, size_t azb, size_t azh, int lda,
    const float* __restrict__ B, size_t bzb, size_t bzh, int ldb,
    const float* __restrict__ bias, float* __restrict__ C,
    size_t czb, size_t czh, int ldc, int K, float scale) {
    constexpr int NI = NT / 32;
    __shared__ __nv_bfloat16 Ah[128][18], Al[128][18];
    __shared__ __nv_bfloat16 Bhs[NT][18], Bls[NT][18];

    int t = threadIdx.x, lane = t & 31, warp = t >> 5;
    int z = blockIdx.z, zb = z / HH, zh = z % HH;
    A += (size_t)zb * azb + (size_t)zh * azh;
    B += (size_t)zb * bzb + (size_t)zh * bzh;
    C += (size_t)zb * czb + (size_t)zh * czh;
    int n0 = blockIdx.x * NT, m0 = blockIdx.y * 128;
    int wm = (warp >> 2) * 64, wn = (warp & 3) * (NT / 4);

    float c[4][NI][4];
#pragma unroll
    for (int mi = 0; mi < 4; mi++)
#pragma unroll
        for (int ni = 0; ni < NI; ni++)
#pragma unroll
            for (int q = 0; q < 4; q++) c[mi][ni][q] = 0.f;

    for (int kt = 0; kt < K; kt += 16) {
        // ---- stage A: 128 x 16, split hi/lo
        {
            int row = t >> 1, kc = (t & 1) * 8;
            const float* Ap = A + (size_t)(m0 + row) * lda + kt + kc;
            float4 v0 = *(const float4*)Ap;
            float4 v1 = *(const float4*)(Ap + 4);
            float vv[8] = {v0.x, v0.y, v0.z, v0.w, v1.x, v1.y, v1.z, v1.w};
#pragma unroll
            for (int j = 0; j < 8; j++) {
                __nv_bfloat16 h = __float2bfloat16(vv[j]);
                Ah[row][kc + j] = h;
                Al[row][kc + j] = __float2bfloat16(vv[j] - __bfloat162float(h));
            }
        }
        // ---- stage B
        if (TRANSB) {
            constexpr int PER = NT / 16;      // 8 (NT=128) or 4 (NT=64)
            int kr = t >> 4, nc = (t & 15) * PER;
            const float* Bp = B + (size_t)(kt + kr) * ldb + n0 + nc;
#pragma unroll
            for (int j4 = 0; j4 < PER; j4 += 4) {
                float4 v = *(const float4*)(Bp + j4);
                float vv[4] = {v.x, v.y, v.z, v.w};
#pragma unroll
                for (int j = 0; j < 4; j++) {
                    __nv_bfloat16 h = __float2bfloat16(vv[j]);
                    Bhs[nc + j4 + j][kr] = h;
                    Bls[nc + j4 + j][kr] =
                        __float2bfloat16(vv[j] - __bfloat162float(h));
                }
            }
        } else {
            // NT == 128: B global [N][K] k-contig
            int row = t >> 1, kc = (t & 1) * 8;
            const float* Bp = B + (size_t)(n0 + row) * ldb + kt + kc;
            float4 v0 = *(const float4*)Bp;
            float4 v1 = *(const float4*)(Bp + 4);
            float vv[8] = {v0.x, v0.y, v0.z, v0.w, v1.x, v1.y, v1.z, v1.w};
#pragma unroll
            for (int j = 0; j < 8; j++) {
                __nv_bfloat16 h = __float2bfloat16(vv[j]);
                Bhs[row][kc + j] = h;
                Bls[row][kc + j] = __float2bfloat16(vv[j] - __bfloat162float(h));
            }
        }
        __syncthreads();

        // ---- fragments + mma
        unsigned bfh[NI][2], bfl[NI][2];
        int kk = (lane & 3) * 2;
#pragma unroll
        for (int ni = 0; ni < NI; ni++) {
            int n = wn + ni * 8 + (lane >> 2);
            bfh[ni][0] = *(const unsigned*)&Bhs[n][kk];
            bfh[ni][1] = *(const unsigned*)&Bhs[n][kk + 8];
            bfl[ni][0] = *(const unsigned*)&Bls[n][kk];
            bfl[ni][1] = *(const unsigned*)&Bls[n][kk + 8];
        }
#pragma unroll
        for (int mi = 0; mi < 4; mi++) {
            int r = wm + mi * 16 + (lane >> 2);
            unsigned a0h = *(const unsigned*)&Ah[r][kk];
            unsigned a1h = *(const unsigned*)&Ah[r + 8][kk];
            unsigned a2h = *(const unsigned*)&Ah[r][kk + 8];
            unsigned a3h = *(const unsigned*)&Ah[r + 8][kk + 8];
            unsigned a0l = *(const unsigned*)&Al[r][kk];
            unsigned a1l = *(const unsigned*)&Al[r + 8][kk];
            unsigned a2l = *(const unsigned*)&Al[r][kk + 8];
            unsigned a3l = *(const unsigned*)&Al[r + 8][kk + 8];
#pragma unroll
            for (int ni = 0; ni < NI; ni++) {
                mma_bf16(c[mi][ni], a0h, a1h, a2h, a3h, bfh[ni][0], bfh[ni][1]);
                mma_bf16(c[mi][ni], a0h, a1h, a2h, a3h, bfl[ni][0], bfl[ni][1]);
                mma_bf16(c[mi][ni], a0l, a1l, a2l, a3l, bfh[ni][0], bfh[ni][1]);
            }
        }
        __syncthreads();
    }

    // ---- epilogue
#pragma unroll
    for (int mi = 0; mi < 4; mi++) {
        int r = m0 + wm + mi * 16 + (lane >> 2);
#pragma unroll
        for (int ni = 0; ni < NI; ni++) {
            int col = n0 + wn + ni * 8 + (lane & 3) * 2;
            float2 v0 = {c[mi][ni][0], c[mi][ni][1]};
            float2 v1 = {c[mi][ni][2], c[mi][ni][3]};
            if (SCALE) {
                v0.x *= scale; v0.y *= scale;
                v1.x *= scale; v1.y *= scale;
            }
            if (BIAS) {
                float2 bb = *(const float2*)(bias + col);
                v0.x += bb.x; v0.y += bb.y;
                v1.x += bb.x; v1.y += bb.y;
            }
            *(float2*)(C + (size_t)r * ldc + col) = v0;
            *(float2*)(C + (size_t)(r + 8) * ldc + col) = v1;
        }
    }
}

// ---------------------------------------------------------------------------
// Selection: init -> hist0 -> scan0 -> segmented cand gather -> final select
// ---------------------------------------------------------------------------
__global__ void sel_init() {
    int bh = blockIdx.x, t = threadIdx.x;
    for (int j = t; j < 2048; j += 256) g_hist[bh * 2048 + j] = 0u;
}

__global__ void hist0() {
    int bh = blockIdx.y, t = threadIdx.x;
    __shared__ unsigned sh[2048];
    for (int j = t; j < 2048; j += 256) sh[j] = 0u;
    __syncthreads();
    const float4* Sp = (const float4*)(g_attn + (size_t)bh * 1048576) +
                       (size_t)blockIdx.x * 8192;
    for (int i = 0; i < 32; i++) {
        float4 v = Sp[i * 256 + t];
        atomicAdd(&sh[fkey(v.x) >> 21], 1u);
        atomicAdd(&sh[fkey(v.y) >> 21], 1u);
        atomicAdd(&sh[fkey(v.z) >> 21], 1u);
        atomicAdd(&sh[fkey(v.w) >> 21], 1u);
    }
    __syncthreads();
    for (int j = t; j < 2048; j += 256) {
        unsigned cc = sh[j];
        if (cc) atomicAdd(&g_hist[bh * 2048 + j], cc);
    }
}

__global__ void scan0() {
    int bh = blockIdx.x, t = threadIdx.x;
    __shared__ unsigned ssum[256];
    __shared__ int s_sel;
    __shared__ unsigned s_kin;
    const unsigned* hist = g_hist + bh * 2048;
    unsigned loc[8], lsum = 0;
#pragma unroll
    for (int i = 0; i < 8; i++) { loc[i] = hist[t * 8 + i]; lsum += loc[i]; }
    ssum[t] = lsum;
    __syncthreads();
    if (t == 0) {
        unsigned k = KTH, cum = 0, kin = k;
        int sel = 255;
        for (int i = 0; i < 256; i++) {
            if (cum + ssum[i] >= k) { sel = i; kin = k - cum; break; }
            cum += ssum[i];
        }
        s_sel = sel; s_kin = kin;
    }
    __syncthreads();
    if (t == s_sel) {
        unsigned kk = s_kin, cum = 0, d = t * 8 + 7, knew = kk;
#pragma unroll
        for (int i = 0; i < 8; i++) {
            if (cum + loc[i] >= kk) { d = t * 8 + i; knew = kk - cum; break; }
            cum += loc[i];
        }
        g_sel[bh] = d;
        g_krem[bh] = (int)knew;
    }
}

// per-block segmented gather with SHARED-MEM counter (no global atomic hotspot)
__global__ void cand_seg() {
    __shared__ int s_cnt;
    int bh = blockIdx.y, t = threadIdx.x;
    unsigned lane = t & 31;
    if (t == 0) s_cnt = 0;
    __syncthreads();
    unsigned sel = g_sel[bh];
    unsigned* seg = g_cand + (size_t)bh * 1048576 + (size_t)blockIdx.x * 32768;
    const float4* Sp = (const float4*)(g_attn + (size_t)bh * 1048576) +
                       (size_t)blockIdx.x * 8192;
    for (int i = 0; i < 32; i++) {
        float4 v = Sp[i * 256 + t];
        unsigned key[4] = {fkey(v.x), fkey(v.y), fkey(v.z), fkey(v.w)};
#pragma unroll
        for (int j = 0; j < 4; j++) {
            bool m = (key[j] >> 21) == sel;
            unsigned bal = __ballot_sync(0xffffffffu, m);
            if (bal) {
                int leader = __ffs(bal) - 1;
                int base = 0;
                if ((int)lane == leader) base = atomicAdd(&s_cnt, __popc(bal));
                base = __shfl_sync(0xffffffffu, base, leader);
                if (m) seg[base + __popc(bal & ((1u << lane) - 1u))] = key[j];
            }
        }
    }
    __syncthreads();
    if (t == 0) g_bcnt[bh * 32 + blockIdx.x] = s_cnt;
}

__global__ void sel_final() {
    int bh = blockIdx.x, t = threadIdx.x;
    __shared__ unsigned sh[2048];
    __shared__ unsigned ssum[256];
    __shared__ int s_sel;
    __shared__ unsigned s_kin;
    __shared__ unsigned s_b1, s_k2;
    const unsigned* base = g_cand + (size_t)bh * 1048576;

    // pass A: bits 20..10
    for (int j = t; j < 2048; j += 256) sh[j] = 0u;
    __syncthreads();
    for (int sg = 0; sg < 32; sg++) {
        int cnt = g_bcnt[bh * 32 + sg];
        const unsigned* cand = base + (size_t)sg * 32768;
        for (int i = t; i < cnt; i += 256)
            atomicAdd(&sh[(cand[i] >> 10) & 2047u], 1u);
    }
    __syncthreads();
    {
        unsigned loc[8], lsum = 0;
#pragma unroll
        for (int i = 0; i < 8; i++) { loc[i] = sh[t * 8 + i]; lsum += loc[i]; }
        ssum[t] = lsum;
        __syncthreads();
        if (t == 0) {
            unsigned k = (unsigned)g_krem[bh], cum = 0, kin = k;
            int sel = 255;
            for (int i = 0; i < 256; i++) {
                if (cum + ssum[i] >= k) { sel = i; kin = k - cum; break; }
                cum += ssum[i];
            }
            s_sel = sel; s_kin = kin;
        }
        __syncthreads();
        if (t == s_sel) {
            unsigned kk = s_kin, cum = 0, d = t * 8 + 7, knew = kk;
#pragma unroll
            for (int i = 0; i < 8; i++) {
                if (cum + loc[i] >= kk) { d = t * 8 + i; knew = kk - cum; break; }
                cum += loc[i];
            }
            s_b1 = d; s_k2 = knew;
        }
        __syncthreads();
    }
    unsigned b1 = s_b1;
    __syncthreads();

    // pass B: bits 9..0
    for (int j = t; j < 1024; j += 256) sh[j] = 0u;
    __syncthreads();
    for (int sg = 0; sg < 32; sg++) {
        int cnt = g_bcnt[bh * 32 + sg];
        const unsigned* cand = base + (size_t)sg * 32768;
        for (int i = t; i < cnt; i += 256) {
            unsigned ky = cand[i];
            if (((ky >> 10) & 2047u) == b1) atomicAdd(&sh[ky & 1023u], 1u);
        }
    }
    __syncthreads();
    {
        unsigned loc[4], lsum = 0;
#pragma unroll
        for (int i = 0; i < 4; i++) { loc[i] = sh[t * 4 + i]; lsum += loc[i]; }
        ssum[t] = lsum;
        __syncthreads();
        if (t == 0) {
            unsigned k = s_k2, cum = 0, kin = k;
            int sel = 255;
            for (int i = 0; i < 256; i++) {
                if (cum + ssum[i] >= k) { sel = i; kin = k - cum; break; }
                cum += ssum[i];
            }
            s_sel = sel; s_kin = kin;
        }
        __syncthreads();
        if (t == s_sel) {
            unsigned kk = s_kin, cum = 0, d = t * 4 + 3;
#pragma unroll
            for (int i = 0; i < 4; i++) {
                if (cum + loc[i] >= kk) { d = t * 4 + i; break; }
                cum += loc[i];
            }
            unsigned key = (g_sel[bh] << 21) | (b1 << 10) | d;
            unsigned bits = (key & 0x80000000u) ? (key ^ 0x80000000u) : ~key;
            g_thr[bh] = __uint_as_float(bits);
        }
    }
}

// ---------------------------------------------------------------------------
// Masked softmax (float4, one block per row, in place)
// ---------------------------------------------------------------------------
__global__ void softmax_mask() {
    int row = blockIdx.x, bh = row >> 10;
    float thr = g_thr[bh];
    float4* S = (float4*)(g_attn + (size_t)row * NN);
    int t = threadIdx.x;
    unsigned lane = t & 31, w = t >> 5;
    __shared__ float red[8];

    float4 vv = S[t];
    float v[4] = {vv.x, vv.y, vv.z, vv.w};
    float mx = -3.0e38f;
#pragma unroll
    for (int i = 0; i < 4; i++) {
        v[i] = (v[i] <= thr) ? -1e9f : v[i];
        mx = fmaxf(mx, v[i]);
    }
#pragma unroll
    for (int o = 16; o; o >>= 1) mx = fmaxf(mx, __shfl_xor_sync(0xffffffffu, mx, o));
    if (lane == 0) red[w] = mx;
    __syncthreads();
    float m = red[0];
#pragma unroll
    for (int i = 1; i < 8; i++) m = fmaxf(m, red[i]);

    float e[4], s = 0.f;
#pragma unroll
    for (int i = 0; i < 4; i++) { e[i] = __expf(v[i] - m); s += e[i]; }
#pragma unroll
    for (int o = 16; o; o >>= 1) s += __shfl_xor_sync(0xffffffffu, s, o);
    __syncthreads();
    if (lane == 0) red[w] = s;
    __syncthreads();
    float tot = 0.f;
#pragma unroll
    for (int i = 0; i < 8; i++) tot += red[i];
    float inv = 1.f / tot;
    float4 ov = {e[0] * inv, e[1] * inv, e[2] * inv, e[3] * inv};
    S[t] = ov;
}

// ---------------------------------------------------------------------------
extern "C" void kernel_launch(void* const* d_in, const int* in_sizes, int n_in,
                              void* d_out, int out_size) {
    const float* x = (const float*)d_in[0];
    const float* W_qkv = (const float*)d_in[1];
    const float* b_qkv = (const float*)d_in[2];
    const float* W_out = (const float*)d_in[3];
    const float* b_out = (const float*)d_in[4];
    float* out = (float*)d_out;

    float* qkv_p; cudaGetSymbolAddress((void**)&qkv_p, g_qkv);
    float* attn_p; cudaGetSymbolAddress((void**)&attn_p, g_attn);
    float* ao_p;  cudaGetSymbolAddress((void**)&ao_p, g_ao);

    // 0. zero hist
    sel_init<<<BH, 256>>>();
    // 1. QKV projection: [4096,768] @ W[768,2304] + bias
    mma_gemm<128, true, true, false><<<dim3(18, 32, 1), 256>>>(
        x, 0, 0, 768, W_qkv, 0, 0, 2304, b_qkv, qkv_p, 0, 0, 2304, 768, 1.f);
    // 2. Scores: Q @ K^T * 0.125  (B operand = K matrix, k-contig, no trans)
    mma_gemm<128, false, false, true><<<dim3(8, 8, BH), 256>>>(
        qkv_p, (size_t)1024 * 2304, 64, 2304,
        qkv_p + 768, (size_t)1024 * 2304, 64, 2304,
        nullptr, attn_p, (size_t)HH * 1048576, 1048576, 1024, 64, 0.125f);
    // 3. Threshold: hist + scan + segmented candidate gather + final select
    hist0<<<dim3(32, BH), 256>>>();
    scan0<<<BH, 256>>>();
    cand_seg<<<dim3(32, BH), 256>>>();
    sel_final<<<BH, 256>>>();
    // 4. Masked softmax in place
    softmax_mask<<<BH * NN, 256>>>();
    // 5. P @ V
    mma_gemm<64, true, false, false><<<dim3(1, 8, BH), 256>>>(
        attn_p, (size_t)HH * 1048576, 1048576, 1024,
        qkv_p + 1536, (size_t)1024 * 2304, 64, 2304,
        nullptr, ao_p, (size_t)1024 * 768, 64, 768, 1024, 1.f);
    // 6. Output projection: [4096,768] @ W[768,768] + bias
    mma_gemm<128, true, true, false><<<dim3(6, 32, 1), 256>>>(
        ao_p, 0, 0, 768, W_out, 0, 0, 768, b_out, out, 0, 0, 768, 768, 1.f);
}